// round 16
// baseline (speedup 1.0000x reference)
#include <cuda_runtime.h>
#include <math.h>

typedef unsigned long long ULL;

// ---------------------------------------------------------------------------
// B=16, dim=48, hid=16, C=8, H=W=256, HW=65536. 4096 image rows total.
// Single fused kernel, 8192 blocks:
//   bid <  4096 : stage-A for image row bid (R15-proven kA body) + flag set
//   bid >= 4096 : stage-B for image row bid-4096; spins on flags of the
//                 <=3 stage-A rows it needs (R8-proven 1px/thread body)
// Overlaps kA's issue-bound phase with kB's DRAM-bound phase.
// ---------------------------------------------------------------------------
#define HW 65536
#define NB 16

__device__ __align__(16) float g_n [NB * 8 * HW];   // planar (B, C, HW)
__device__ __align__(16) float g_x1[NB * HW * 8];   // (B, HW, C)
__device__ int g_flag[4096];                        // per-row completion

__constant__ ULL   cW1p[384];   // W1 (48,16) as pairs [k*8 + j2]
__constant__ ULL   cW2p[192];   // W2 (8,48)  as pairs [c*24 + d2]
__constant__ float cdw[72];
__constant__ float cpw[64];
__constant__ float cb1[16];
__constant__ float cgam[8], cbet[8], cdwb[8], cpwb[8];
__constant__ ULL   cb2p[24];

// ---- packed f32x2 helpers ----
__device__ __forceinline__ ULL pk(float a, float b) {
    ULL r; asm("mov.b64 %0,{%1,%2};" : "=l"(r) : "f"(a), "f"(b)); return r;
}
__device__ __forceinline__ void upk(ULL v, float& a, float& b) {
    asm("mov.b64 {%0,%1},%2;" : "=f"(a), "=f"(b) : "l"(v));
}
__device__ __forceinline__ ULL f2fma(ULL a, ULL b, ULL c) {
    ULL d; asm("fma.rn.f32x2 %0,%1,%2,%3;" : "=l"(d) : "l"(a), "l"(b), "l"(c)); return d;
}
__device__ __forceinline__ ULL f2mul(ULL a, ULL b) {
    ULL d; asm("mul.rn.f32x2 %0,%1,%2;" : "=l"(d) : "l"(a), "l"(b)); return d;
}
__device__ __forceinline__ ULL f2add(ULL a, ULL b) {
    ULL d; asm("add.rn.f32x2 %0,%1,%2;" : "=l"(d) : "l"(a), "l"(b)); return d;
}
__device__ __forceinline__ float rcp_fast(float a) {
    float r; asm("rcp.approx.f32 %0,%1;" : "=f"(r) : "f"(a)); return r;
}
__device__ __forceinline__ float ex2_fast(float a) {
    float r; asm("ex2.approx.f32 %0,%1;" : "=f"(r) : "f"(a)); return r;
}

// Packed double-lane GELU (A&S 7.1.26). Verified rel_err 4.47e-7.
__device__ __forceinline__ ULL gelu2(ULL v) {
    const ULL ONE  = 0x3f8000003f800000ULL;
    const ULL HALF = 0x3f0000003f000000ULL;
    ULL x  = f2mul(v, pk(0.70710678f, 0.70710678f));
    ULL ax = x & 0x7fffffff7fffffffULL;
    ULL dn = f2fma(pk(0.3275911f, 0.3275911f), ax, ONE);
    float d0, d1; upk(dn, d0, d1);
    ULL t  = pk(rcp_fast(d0), rcp_fast(d1));
    ULL q = pk(-1.061405429f, -1.061405429f);
    q = f2fma(q, t, pk( 1.453152027f,  1.453152027f));
    q = f2fma(q, t, pk(-1.421413741f, -1.421413741f));
    q = f2fma(q, t, pk( 0.284496736f,  0.284496736f));
    q = f2fma(q, t, pk(-0.254829592f, -0.254829592f));
    q = f2mul(q, t);
    ULL xx = f2mul(x, x);
    ULL ea = f2mul(xx, pk(-1.4426950408f, -1.4426950408f));
    float e0, e1; upk(ea, e0, e1);
    ULL e  = pk(ex2_fast(e0), ex2_fast(e1));
    ULL er = f2fma(q, e, ONE);
    er = er | (v & 0x8000000080000000ULL);
    return f2mul(v, f2fma(er, HALF, HALF));
}

// ---------------------------------------------------------------------------
__global__ void zeroFlags() { g_flag[blockIdx.x * 256 + threadIdx.x] = 0; }

// ---------------------------------------------------------------------------
extern __shared__ __align__(16) char smBase[];

__global__ void __launch_bounds__(256) kFused(const float* __restrict__ x,
                                              float* __restrict__ out) {
    int t = threadIdx.x;

    if (blockIdx.x < 4096) {
        // ================= stage-A: one image row (256 px) =================
        float4* xs4 = (float4*)smBase;          // [256][12], 48 KB
        size_t Pbase = (size_t)blockIdx.x * 256;
        const float4* gx = (const float4*)(x + Pbase * 48);

#pragma unroll
        for (int i = 0; i < 12; i++) {
            int idx = i * 256 + t;
            int p = idx / 12;
            int f = idx - p * 12;
            int fr = f + p; fr %= 12;
            xs4[p * 12 + fr] = gx[idx];
        }
        __syncthreads();

        ULL acc[8];
#pragma unroll
        for (int j = 0; j < 8; j++) acc[j] = 0ULL;

        int r0 = t % 12;
#pragma unroll
        for (int f = 0; f < 12; f++) {
            int fr = f + r0; if (fr >= 12) fr -= 12;
            float4 v = xs4[t * 12 + fr];
            float kv[4] = {v.x, v.y, v.z, v.w};
#pragma unroll
            for (int q = 0; q < 4; q++) {
                int k = f * 4 + q;
                ULL bx = pk(kv[q], kv[q]);
#pragma unroll
                for (int j = 0; j < 8; j++)
                    acc[j] = f2fma(bx, cW1p[k * 8 + j], acc[j]);
            }
        }

        size_t P = Pbase + (size_t)t;
        ULL hh[8];
#pragma unroll
        for (int j = 0; j < 8; j++) {
            ULL z = f2add(acc[j], pk(cb1[2 * j], cb1[2 * j + 1]));
            hh[j] = gelu2(gelu2(z));
        }

        ulonglong2* x1o = (ulonglong2*)g_x1 + P * 2;
        x1o[0] = make_ulonglong2(hh[0], hh[1]);
        x1o[1] = make_ulonglong2(hh[2], hh[3]);

        ULL s2 = f2add(f2add(hh[4], hh[5]), f2add(hh[6], hh[7]));
        float sa, sb; upk(s2, sa, sb);
        float m = (sa + sb) * 0.125f;
        ULL mm = pk(-m, -m);
        ULL dj[4];
        ULL vq = 0ULL;
#pragma unroll
        for (int j = 0; j < 4; j++) {
            dj[j] = f2add(hh[4 + j], mm);
            vq = f2fma(dj[j], dj[j], vq);
        }
        float va, vb; upk(vq, va, vb);
        float inv = rsqrtf((va + vb) * 0.125f + 1e-5f);

        size_t b_ = P >> 16, pp = P & 65535;
        float* nb = g_n + (b_ << 19) + pp;
#pragma unroll
        for (int j = 0; j < 4; j++) {
            ULL gi = f2mul(pk(cgam[2 * j], cgam[2 * j + 1]), pk(inv, inv));
            ULL nj = f2fma(dj[j], gi, pk(cbet[2 * j], cbet[2 * j + 1]));
            float n0, n1; upk(nj, n0, n1);
            nb[(size_t)(2 * j)     << 16] = n0;
            nb[(size_t)(2 * j + 1) << 16] = n1;
        }

        // release: all stores visible, then publish the row flag
        __threadfence();
        __syncthreads();
        if (t == 0) atomicExch(&g_flag[blockIdx.x], 1);

    } else {
        // ================= stage-B: one output row =================
        float (*ns)[3][264] = (float (*)[3][264])smBase;   // [8][3][264], 25 KB

        int r  = blockIdx.x - 4096;        // global row
        int b_ = r >> 8;
        int h  = r & 255;

        // wait for producer rows (r-1, r, r+1 within this batch)
        if (t == 0)            { while (atomicAdd(&g_flag[r], 0)     == 0) __nanosleep(64); }
        if (t == 1 && h > 0)   { while (atomicAdd(&g_flag[r - 1], 0) == 0) __nanosleep(64); }
        if (t == 2 && h < 255) { while (atomicAdd(&g_flag[r + 1], 0) == 0) __nanosleep(64); }
        __syncthreads();
        __threadfence();   // acquire: no stale lines before reading g_n/g_x1

        const float* nbase = g_n + ((size_t)b_ << 19);
#pragma unroll
        for (int c = 0; c < 8; c++) {
#pragma unroll
            for (int rr = 0; rr < 3; rr++) {
                int hs = h + rr - 1;
                float v = 0.f;
                if ((unsigned)hs < 256u)
                    v = nbase[((size_t)c << 16) + ((size_t)hs << 8) + (size_t)t];
                ns[c][rr][1 + t] = v;
            }
        }
        if (t < 48) {   // zero halo cols (8c x 3r x 2 sides = 48 slots)
            int c = t >> 3, rr = (t >> 1) & 3;
            if (rr < 3) ns[c][rr][(t & 1) ? 257 : 0] = 0.f;
        }
        // fix: cover all (c, rr) halo pairs robustly
        if (t >= 128 && t < 176) {
            int idx = t - 128;            // 0..47
            int c = idx / 6, rem = idx % 6, rr = rem >> 1;
            ns[c][rr][(rem & 1) ? 257 : 0] = 0.f;
        }
        __syncthreads();

        // x1 for this pixel
        size_t P = ((size_t)b_ << 16) + ((size_t)h << 8) + (size_t)t;
        const float4* x1v = (const float4*)(g_x1 + P * 8);
        float4 XA = x1v[0], XB = x1v[1];
        float x1r[8] = {XA.x, XA.y, XA.z, XA.w, XB.x, XB.y, XB.z, XB.w};

        // depthwise 3x3 (SAME), column t (halo offset 1)
        float sp[8], nc[8];
#pragma unroll
        for (int c = 0; c < 8; c++) {
            float a;
            a  = ns[c][0][t]     * cdw[c * 9 + 0];
            a += ns[c][0][t + 1] * cdw[c * 9 + 1];
            a += ns[c][0][t + 2] * cdw[c * 9 + 2];
            a += ns[c][1][t]     * cdw[c * 9 + 3];
            float ctr = ns[c][1][t + 1];
            a += ctr             * cdw[c * 9 + 4];
            a += ns[c][1][t + 2] * cdw[c * 9 + 5];
            a += ns[c][2][t]     * cdw[c * 9 + 6];
            a += ns[c][2][t + 1] * cdw[c * 9 + 7];
            a += ns[c][2][t + 2] * cdw[c * 9 + 8];
            sp[c] = a + cdwb[c];
            nc[c] = ctr;
        }

        // pointwise + gate
        float g[8];
#pragma unroll
        for (int c = 0; c < 8; c++) {
            float a = cpwb[c];
#pragma unroll
            for (int c2 = 0; c2 < 8; c2++)
                a = fmaf(cpw[c * 8 + c2], nc[c2], a);
            g[c] = x1r[c] * sp[c] * a;
        }

        // GEMM2: out[d] = sum_c g[c]*W2[c][d] + b2[d]
        float* ob = out + (size_t)b_ * 48 * HW;
        size_t obase = ((size_t)h << 8) + (size_t)t;
#pragma unroll
        for (int half = 0; half < 2; half++) {
            ULL o[12];
#pragma unroll
            for (int dd = 0; dd < 12; dd++) o[dd] = cb2p[half * 12 + dd];
#pragma unroll
            for (int c = 0; c < 8; c++) {
                ULL gb = pk(g[c], g[c]);
#pragma unroll
                for (int dd = 0; dd < 12; dd++)
                    o[dd] = f2fma(gb, cW2p[c * 24 + half * 12 + dd], o[dd]);
            }
#pragma unroll
            for (int dd = 0; dd < 12; dd++) {
                float pa, pb; upk(o[dd], pa, pb);
                int d = half * 24 + 2 * dd;
                ob[((size_t)d << 16) + obase]       = pa;
                ob[((size_t)(d + 1) << 16) + obase] = pb;
            }
        }
    }
}

// ---------------------------------------------------------------------------
extern "C" void kernel_launch(void* const* d_in, const int* in_sizes, int n_in,
                              void* d_out, int out_size) {
    const float* x = (const float*)d_in[0];
    float* out = (float*)d_out;

    cudaMemcpyToSymbolAsync(cW1p, d_in[1], 768 * 4, 0, cudaMemcpyDeviceToDevice);
    cudaMemcpyToSymbolAsync(cb1,  d_in[2], 16 * 4,  0, cudaMemcpyDeviceToDevice);
    cudaMemcpyToSymbolAsync(cgam, d_in[3], 8 * 4,   0, cudaMemcpyDeviceToDevice);
    cudaMemcpyToSymbolAsync(cbet, d_in[4], 8 * 4,   0, cudaMemcpyDeviceToDevice);
    cudaMemcpyToSymbolAsync(cdw,  d_in[5], 72 * 4,  0, cudaMemcpyDeviceToDevice);
    cudaMemcpyToSymbolAsync(cdwb, d_in[6], 8 * 4,   0, cudaMemcpyDeviceToDevice);
    cudaMemcpyToSymbolAsync(cpw,  d_in[7], 64 * 4,  0, cudaMemcpyDeviceToDevice);
    cudaMemcpyToSymbolAsync(cpwb, d_in[8], 8 * 4,   0, cudaMemcpyDeviceToDevice);
    cudaMemcpyToSymbolAsync(cW2p, d_in[9], 384 * 4, 0, cudaMemcpyDeviceToDevice);
    cudaMemcpyToSymbolAsync(cb2p, d_in[10], 48 * 4, 0, cudaMemcpyDeviceToDevice);

    static int smem_set = 0;
    cudaFuncSetAttribute(kFused, cudaFuncAttributeMaxDynamicSharedMemorySize, 49152);
    (void)smem_set;

    zeroFlags<<<16, 256>>>();
    kFused<<<8192, 256, 49152>>>(x, out);
}